// round 6
// baseline (speedup 1.0000x reference)
#include <cuda_runtime.h>
#include <cuda_bf16.h>

// LocalFeatureAggregation: B=4, N=16384, K=16, C=64, D=64
// out[p, 0:64]   = mean_k leaky( geom[p,k,:] @ w^T + b )
// out[p, 64:128] = mean_k features[b, idx[p,k], :]
//
// Two kernels:
//  1) transpose geom [B,N,16,4] -> g_geomT [B,N,4,16] (coalesced smem transpose)
//  2) main: one warp per point.
//     MLP packs over k-pairs: lane l computes channels {l, l+32}; weights are
//     duplicated f32x2 pairs (built once), geometry pairs come straight out of
//     uniform LDG.128 float4 registers (v.xy / v.zw). No shared memory on the
//     geometry path -> 16 broadcast wavefronts/point instead of ~70.
//     Gather: lanes 0-15 even k rows, 16-31 odd; 8 LDG.128; shfl combine.

#define KNB 16
#define FULLMASK 0xffffffffu

__device__ float g_geomT[4u * 16384u * 64u];   // [B,N,4,16] scratch (16 MB)

__device__ __forceinline__ unsigned long long pk2(float x, float y) {
    unsigned long long r;
    asm("mov.b64 %0, {%1,%2};" : "=l"(r) : "f"(x), "f"(y));
    return r;
}
__device__ __forceinline__ void upk2(unsigned long long v, float& x, float& y) {
    asm("mov.b64 {%0,%1}, %2;" : "=f"(x), "=f"(y) : "l"(v));
}
__device__ __forceinline__ unsigned long long fma2(unsigned long long a,
                                                   unsigned long long b,
                                                   unsigned long long c) {
    unsigned long long d;
    asm("fma.rn.f32x2 %0, %1, %2, %3;" : "=l"(d) : "l"(a), "l"(b), "l"(c));
    return d;
}
__device__ __forceinline__ unsigned long long add2(unsigned long long a,
                                                   unsigned long long b) {
    unsigned long long d;
    asm("add.rn.f32x2 %0, %1, %2;" : "=l"(d) : "l"(a), "l"(b));
    return d;
}
__device__ __forceinline__ unsigned long long mul2(unsigned long long a,
                                                   unsigned long long b) {
    unsigned long long d;
    asm("mul.rn.f32x2 %0, %1, %2;" : "=l"(d) : "l"(a), "l"(b));
    return d;
}

// ---- kernel 1: per-point 16x4 -> 4x16 transpose, fully coalesced ----
__global__ __launch_bounds__(256) void transpose_geom(
    const float4* __restrict__ gin)    // [points*16] float4 (k-major)
{
    __shared__ float sm[16][4][17];
    const int t = threadIdx.x;
    const int pt = t >> 4;             // local point 0..15
    const int q  = t & 15;
    const float4 v = gin[blockIdx.x * 256 + t];     // point pt, k=q, dims 0..3
    sm[pt][0][q] = v.x;
    sm[pt][1][q] = v.y;
    sm[pt][2][q] = v.z;
    sm[pt][3][q] = v.w;
    __syncthreads();
    const int i  = q >> 2;
    const int kg = (q & 3) * 4;
    float4 o;
    o.x = sm[pt][i][kg + 0];
    o.y = sm[pt][i][kg + 1];
    o.z = sm[pt][i][kg + 2];
    o.w = sm[pt][i][kg + 3];
    ((float4*)g_geomT)[blockIdx.x * 256 + t] = o;   // point pt, dim i, k kg..kg+3
}

// ---- kernel 2: main ----
__global__ __launch_bounds__(256) void lfa_kernel(
    const float* __restrict__ features,       // [B, N, 64]
    const float* __restrict__ w,              // [64, 4]
    const float* __restrict__ bias,           // [64]
    const int* __restrict__ nbr,              // [B, N, 16] int32
    float* __restrict__ out,                  // [B, N, 128]
    int points, int n_log2)
{
    __shared__ float4 ws[64];
    __shared__ float  bs[64];

    const int tid = threadIdx.x;
    if (tid < 64) {
        ws[tid] = ((const float4*)w)[tid];
        bs[tid] = bias[tid];
    }
    __syncthreads();

    const int warp = tid >> 5;
    const int lane = tid & 31;
    const int p = blockIdx.x * 8 + warp;
    if (p >= points) return;                          // uniform per warp

    // ---- neighbor indices: 4 uniform LDG.128 ----
    const int4* nb4 = (const int4*)(nbr + (size_t)p * KNB);
    const int4 q0 = nb4[0], q1 = nb4[1], q2 = nb4[2], q3 = nb4[3];
    int idx[16];
    idx[0]=q0.x; idx[1]=q0.y; idx[2]=q0.z; idx[3]=q0.w;
    idx[4]=q1.x; idx[5]=q1.y; idx[6]=q1.z; idx[7]=q1.w;
    idx[8]=q2.x; idx[9]=q2.y; idx[10]=q2.z; idx[11]=q2.w;
    idx[12]=q3.x; idx[13]=q3.y; idx[14]=q3.z; idx[15]=q3.w;

    // ---- duplicated weight/bias pairs (loop-invariant) ----
    const float4 wA = ws[lane];           // channel d0 = lane
    const float4 wB = ws[lane + 32];      // channel d1 = lane+32
    const unsigned long long wa0 = pk2(wA.x, wA.x), wa1 = pk2(wA.y, wA.y);
    const unsigned long long wa2 = pk2(wA.z, wA.z), wa3 = pk2(wA.w, wA.w);
    const unsigned long long wb0 = pk2(wB.x, wB.x), wb1 = pk2(wB.y, wB.y);
    const unsigned long long wb2 = pk2(wB.z, wB.z), wb3 = pk2(wB.w, wB.w);
    const unsigned long long bpa = pk2(bs[lane], bs[lane]);
    const unsigned long long bpb = pk2(bs[lane + 32], bs[lane + 32]);
    const unsigned long long c055 = pk2(0.55f, 0.55f);
    const unsigned long long c045 = pk2(0.45f, 0.45f);
    const unsigned long long ABSM = 0x7fffffff7fffffffULL;

    const int bIdx = p >> n_log2;
    const int nPerB = 1 << n_log2;
    const int h = lane >> 4;            // half-warp: 0 -> even k, 1 -> odd k
    const int c = lane & 15;            // float4 slot within feature row
    const ulonglong2* featq =
        (const ulonglong2*)(features + (size_t)bIdx * nPerB * 64) + c;

    const float4* gT = (const float4*)g_geomT + (size_t)p * 16;

    unsigned long long accA = 0ull, accB = 0ull;   // MLP acc (ch lane / lane+32)
    unsigned long long gx = 0ull, gy = 0ull;       // gather acc

#pragma unroll
    for (int g = 0; g < 4; g++) {
        // geometry: 4 uniform LDG.128 (broadcast), k rows 4g..4g+3
        const float4 v0 = gT[g];          // dim0, k 4g..4g+3
        const float4 v1 = gT[4 + g];
        const float4 v2 = gT[8 + g];
        const float4 v3 = gT[12 + g];

        // gather rows 4g..4g+3 (2 LDG.128, two rows each)
        {
            const int r = h ? idx[4 * g + 1] : idx[4 * g + 0];
            const ulonglong2 fv = featq[(size_t)r * 16];
            gx = add2(gx, fv.x); gy = add2(gy, fv.y);
        }
        {
            const int r = h ? idx[4 * g + 3] : idx[4 * g + 2];
            const ulonglong2 fv = featq[(size_t)r * 16];
            gx = add2(gx, fv.x); gy = add2(gy, fv.y);
        }

        // k-pair (4g, 4g+1): .xy components
        unsigned long long pe0 = pk2(v0.x, v0.y), pe1 = pk2(v1.x, v1.y);
        unsigned long long pe2 = pk2(v2.x, v2.y), pe3 = pk2(v3.x, v3.y);
        unsigned long long tA = fma2(pe0, wa0, bpa);
        tA = fma2(pe1, wa1, tA); tA = fma2(pe2, wa2, tA); tA = fma2(pe3, wa3, tA);
        accA = fma2(tA, c055, accA); accA = fma2(tA & ABSM, c045, accA);
        unsigned long long tB = fma2(pe0, wb0, bpb);
        tB = fma2(pe1, wb1, tB); tB = fma2(pe2, wb2, tB); tB = fma2(pe3, wb3, tB);
        accB = fma2(tB, c055, accB); accB = fma2(tB & ABSM, c045, accB);

        // k-pair (4g+2, 4g+3): .zw components
        unsigned long long po0 = pk2(v0.z, v0.w), po1 = pk2(v1.z, v1.w);
        unsigned long long po2 = pk2(v2.z, v2.w), po3 = pk2(v3.z, v3.w);
        tA = fma2(po0, wa0, bpa);
        tA = fma2(po1, wa1, tA); tA = fma2(po2, wa2, tA); tA = fma2(po3, wa3, tA);
        accA = fma2(tA, c055, accA); accA = fma2(tA & ABSM, c045, accA);
        tB = fma2(po0, wb0, bpb);
        tB = fma2(po1, wb1, tB); tB = fma2(po2, wb2, tB); tB = fma2(po3, wb3, tB);
        accB = fma2(tB, c055, accB); accB = fma2(tB & ABSM, c045, accB);
    }

    // ---- epilogue ----
    float aLo, aHi, bLo, bHi;
    upk2(accA, aLo, aHi);
    upk2(accB, bLo, bHi);
    const float mA = (aLo + aHi) * 0.0625f;
    const float mB = (bLo + bHi) * 0.0625f;

    const unsigned long long ox = __shfl_down_sync(FULLMASK, gx, 16);
    const unsigned long long oy = __shfl_down_sync(FULLMASK, gy, 16);

    const size_t ob = (size_t)p * 128;
    out[ob + lane]      = mA;                 // channels [0,32)
    out[ob + 32 + lane] = mB;                 // channels [32,64)

    if (lane < 16) {
        const unsigned long long inv = pk2(0.0625f, 0.0625f);
        ulonglong2 res;
        res.x = mul2(add2(gx, ox), inv);
        res.y = mul2(add2(gy, oy), inv);
        ((ulonglong2*)(out + ob + 64))[c] = res;   // channels [64,128)
    }
}

extern "C" void kernel_launch(void* const* d_in, const int* in_sizes, int n_in,
                              void* d_out, int out_size) {
    const float* features    = (const float*)d_in[0];
    const float* geom        = (const float*)d_in[1];
    const float* w           = (const float*)d_in[2];
    const float* bias        = (const float*)d_in[3];
    const int*   nbr         = (const int*)d_in[4];    // int32 (JAX x64 off)
    float* out               = (float*)d_out;

    const int points = in_sizes[0] / 64;          // B*N = 65536
    const int n_log2 = 14;                        // N = 16384 per batch

    transpose_geom<<<points / 16, 256>>>((const float4*)geom);

    const int blocks = (points + 7) / 8;
    (void)n_in; (void)out_size;
    lfa_kernel<<<blocks, 256>>>(features, w, bias, nbr, out, points, n_log2);
}

// round 8
// speedup vs baseline: 1.1420x; 1.1420x over previous
#include <cuda_runtime.h>
#include <cuda_bf16.h>

// LocalFeatureAggregation: B=4, N=16384, K=16, C=64, D=64
// out[p, 0:64]   = mean_k leaky( geom[p,k,:] @ w^T + b )
// out[p, 64:128] = mean_k features[b, idx[p,k], :]
//
// One warp per point, k split across half-warps (exact: mean over k is additive).
//  MLP:   half-warp h handles k = 2s+h (s=0..7). Lane (h,c) owns channels
//         {c, c+16, c+32, c+48} as two packed f32x2 pairs. Geometry read as
//         one LDG.128 per step with two distinct 16B addresses (one per half)
//         -> 4KB/point register writeback instead of 8KB. Final shfl_xor(16)
//         combines the two k-halves.
//  Gather: lanes 0-15 even k rows, 16-31 odd; 8 LDG.128 (two rows each);
//         indices via one distinct LDG.32 + per-step shfl.idx (off the L1 path).

#define KNB 16
#define FULLMASK 0xffffffffu

__device__ __forceinline__ unsigned long long pk2(float x, float y) {
    unsigned long long r;
    asm("mov.b64 %0, {%1,%2};" : "=l"(r) : "f"(x), "f"(y));
    return r;
}
__device__ __forceinline__ void upk2(unsigned long long v, float& x, float& y) {
    asm("mov.b64 {%0,%1}, %2;" : "=f"(x), "=f"(y) : "l"(v));
}
__device__ __forceinline__ unsigned long long fma2(unsigned long long a,
                                                   unsigned long long b,
                                                   unsigned long long c) {
    unsigned long long d;
    asm("fma.rn.f32x2 %0, %1, %2, %3;" : "=l"(d) : "l"(a), "l"(b), "l"(c));
    return d;
}
__device__ __forceinline__ unsigned long long add2(unsigned long long a,
                                                   unsigned long long b) {
    unsigned long long d;
    asm("add.rn.f32x2 %0, %1, %2;" : "=l"(d) : "l"(a), "l"(b));
    return d;
}
__device__ __forceinline__ unsigned long long mul2(unsigned long long a,
                                                   unsigned long long b) {
    unsigned long long d;
    asm("mul.rn.f32x2 %0, %1, %2;" : "=l"(d) : "l"(a), "l"(b));
    return d;
}
__device__ __forceinline__ unsigned long long shflxor16(unsigned long long v) {
    unsigned lo = (unsigned)v, hi = (unsigned)(v >> 32);
    lo = __shfl_xor_sync(FULLMASK, lo, 16);
    hi = __shfl_xor_sync(FULLMASK, hi, 16);
    return ((unsigned long long)hi << 32) | lo;
}

__global__ __launch_bounds__(256) void lfa_kernel(
    const float* __restrict__ features,       // [B, N, 64]
    const float4* __restrict__ geom4,         // [B*N*16] float4 (k-major)
    const float* __restrict__ w,              // [64, 4]
    const float* __restrict__ bias,           // [64]
    const int* __restrict__ nbr,              // [B, N, 16] int32
    float* __restrict__ out,                  // [B, N, 128]
    int points, int n_log2)
{
    __shared__ float4 ws[64];
    __shared__ float  bs[64];

    const int tid = threadIdx.x;
    if (tid < 64) {
        ws[tid] = ((const float4*)w)[tid];
        bs[tid] = bias[tid];
    }
    __syncthreads();

    const int warp = tid >> 5;
    const int lane = tid & 31;
    const int p = blockIdx.x * 8 + warp;
    if (p >= points) return;                          // uniform per warp

    const int h = lane >> 4;            // half-warp id
    const int c = lane & 15;

    // ---- neighbor indices: distinct LDG.32 (64B), delivered later via shfl ----
    const int myidx = nbr[(size_t)p * KNB + c];

    // ---- per-lane weight/bias pairs for channels {c,c+32} and {c+16,c+48} ----
    const float4 wP0a = ws[c],      wP0b = ws[c + 32];
    const float4 wP1a = ws[c + 16], wP1b = ws[c + 48];
    const unsigned long long w00 = pk2(wP0a.x, wP0b.x), w01 = pk2(wP0a.y, wP0b.y);
    const unsigned long long w02 = pk2(wP0a.z, wP0b.z), w03 = pk2(wP0a.w, wP0b.w);
    const unsigned long long w10 = pk2(wP1a.x, wP1b.x), w11 = pk2(wP1a.y, wP1b.y);
    const unsigned long long w12 = pk2(wP1a.z, wP1b.z), w13 = pk2(wP1a.w, wP1b.w);
    const unsigned long long bP0 = pk2(bs[c], bs[c + 32]);
    const unsigned long long bP1 = pk2(bs[c + 16], bs[c + 48]);
    const unsigned long long c055 = pk2(0.55f, 0.55f);
    const unsigned long long c045 = pk2(0.45f, 0.45f);
    const unsigned long long ABSM = 0x7fffffff7fffffffULL;

    const int bIdx = p >> n_log2;
    const int nPerB = 1 << n_log2;
    const ulonglong2* featq =
        (const ulonglong2*)(features + (size_t)bIdx * nPerB * 64) + c;
    const float4* gpt = geom4 + (size_t)p * KNB;

    unsigned long long accP0 = 0ull, accP1 = 0ull;   // MLP partial (this k-half)
    unsigned long long gx = 0ull, gy = 0ull;         // gather acc

#pragma unroll
    for (int s = 0; s < 8; s++) {
        // geometry for this half's k = 2s+h: one LDG.128, 2 distinct 16B addrs
        const float4 v = gpt[2 * s + h];

        // gather row idx[2s+h] (index via shuffle, not L1)
        const int r = __shfl_sync(FULLMASK, myidx, 2 * s + h);
        const ulonglong2 fv = featq[(size_t)r * 16];
        gx = add2(gx, fv.x);
        gy = add2(gy, fv.y);

        // MLP for k = 2s+h, two packed channel pairs
        const unsigned long long g0 = pk2(v.x, v.x);
        const unsigned long long g1 = pk2(v.y, v.y);
        const unsigned long long g2 = pk2(v.z, v.z);
        const unsigned long long g3 = pk2(v.w, v.w);

        unsigned long long t0 = fma2(g0, w00, bP0);
        t0 = fma2(g1, w01, t0); t0 = fma2(g2, w02, t0); t0 = fma2(g3, w03, t0);
        accP0 = fma2(t0, c055, accP0);
        accP0 = fma2(t0 & ABSM, c045, accP0);

        unsigned long long t1 = fma2(g0, w10, bP1);
        t1 = fma2(g1, w11, t1); t1 = fma2(g2, w12, t1); t1 = fma2(g3, w13, t1);
        accP1 = fma2(t1, c055, accP1);
        accP1 = fma2(t1 & ABSM, c045, accP1);
    }

    // ---- combine k-halves and write MLP output ----
    const unsigned long long inv = pk2(0.0625f, 0.0625f);
    accP0 = mul2(add2(accP0, shflxor16(accP0)), inv);
    accP1 = mul2(add2(accP1, shflxor16(accP1)), inv);

    float p0l, p0h, p1l, p1h;
    upk2(accP0, p0l, p0h);        // (ch c, ch c+32)
    upk2(accP1, p1l, p1h);        // (ch c+16, ch c+48)

    const size_t ob = (size_t)p * 128;
    const float e0 = h ? p0h : p0l;           // ch c + 32h
    const float e1 = h ? p1h : p1l;           // ch c + 16 + 32h
    out[ob + c + 32 * h]      = e0;
    out[ob + c + 16 + 32 * h] = e1;

    // ---- combine gather halves, write [64,128) ----
    const unsigned long long ox = __shfl_down_sync(FULLMASK, gx, 16);
    const unsigned long long oy = __shfl_down_sync(FULLMASK, gy, 16);
    if (lane < 16) {
        ulonglong2 res;
        res.x = mul2(add2(gx, ox), inv);
        res.y = mul2(add2(gy, oy), inv);
        ((ulonglong2*)(out + ob + 64))[c] = res;
    }
}

extern "C" void kernel_launch(void* const* d_in, const int* in_sizes, int n_in,
                              void* d_out, int out_size) {
    const float* features    = (const float*)d_in[0];
    const float* geom        = (const float*)d_in[1];
    const float* w           = (const float*)d_in[2];
    const float* bias        = (const float*)d_in[3];
    const int*   nbr         = (const int*)d_in[4];    // int32 (JAX x64 off)
    float* out               = (float*)d_out;

    const int points = in_sizes[0] / 64;          // B*N = 65536
    const int n_log2 = 14;                        // N = 16384 per batch

    const int blocks = (points + 7) / 8;
    (void)n_in; (void)out_size;
    lfa_kernel<<<blocks, 256>>>(features, (const float4*)geom, w, bias, nbr,
                                out, points, n_log2);
}